// round 5
// baseline (speedup 1.0000x reference)
#include <cuda_runtime.h>
#include <math.h>

// Problem dims
#define BB 2
#define SS 2048
#define DD 1024
#define HH 16
#define HD 64
#define ROWS (BB*SS)          // 4096
#define EPS 1e-6f

// ---------------- scratch (device globals; no allocation allowed) ----------
__device__ float g_xn  [ROWS * DD];          // layernorm output
__device__ float g_qkv [ROWS * 3 * DD];      // qkv projection
__device__ float g_q   [BB * HH * SS * HD];  // [b,h,s,d]
__device__ float g_k   [BB * HH * SS * HD];
__device__ float g_v   [BB * HH * SS * HD];
__device__ float g_attn[ROWS * DD];          // attention out, [b,s,h*64+d]

// ---------------- kernel 1: row LayerNorm over D=1024 ---------------------
__global__ __launch_bounds__(256) void ln_kernel(
    const float* __restrict__ x, const float* __restrict__ scale,
    const float* __restrict__ bias, float* __restrict__ y)
{
    __shared__ float sh[8];
    const int t = threadIdx.x;
    const size_t row = blockIdx.x;
    const float* xr = x + row * DD;

    float v0 = xr[t], v1 = xr[t + 256], v2 = xr[t + 512], v3 = xr[t + 768];

    float s = v0 + v1 + v2 + v3;
    #pragma unroll
    for (int o = 16; o; o >>= 1) s += __shfl_xor_sync(0xffffffffu, s, o);
    if ((t & 31) == 0) sh[t >> 5] = s;
    __syncthreads();
    float tot = 0.f;
    #pragma unroll
    for (int i = 0; i < 8; i++) tot += sh[i];
    const float mean = tot * (1.f / 1024.f);

    float a0 = v0 - mean, a1 = v1 - mean, a2 = v2 - mean, a3 = v3 - mean;
    float sq = a0*a0 + a1*a1 + a2*a2 + a3*a3;
    #pragma unroll
    for (int o = 16; o; o >>= 1) sq += __shfl_xor_sync(0xffffffffu, sq, o);
    __syncthreads();
    if ((t & 31) == 0) sh[t >> 5] = sq;
    __syncthreads();
    float tsq = 0.f;
    #pragma unroll
    for (int i = 0; i < 8; i++) tsq += sh[i];
    const float rstd = rsqrtf(tsq * (1.f / 1024.f) + EPS);

    float* yr = y + row * DD;
    yr[t      ] = a0 * rstd * scale[t      ] + bias[t      ];
    yr[t + 256] = a1 * rstd * scale[t + 256] + bias[t + 256];
    yr[t + 512] = a2 * rstd * scale[t + 512] + bias[t + 512];
    yr[t + 768] = a3 * rstd * scale[t + 768] + bias[t + 768];
}

// ---------------- kernel 2: SGEMM 128x128x8, 8x8 per thread, + bias -------
__global__ __launch_bounds__(256) void sgemm_bias(
    const float* __restrict__ A, const float* __restrict__ B,
    const float* __restrict__ bias, float* __restrict__ C,
    int M, int N, int K)
{
    __shared__ float As[8][128];
    __shared__ float Bs[8][128];

    const int tid = threadIdx.x;
    const int tx = tid & 15;      // 0..15  -> N direction
    const int ty = tid >> 4;      // 0..15  -> M direction
    const int rowBase = blockIdx.y * 128;
    const int colBase = blockIdx.x * 128;

    const int aRow = tid >> 1;            // 0..127
    const int aCol = (tid & 1) * 4;       // 0 or 4
    const int bRow = tid >> 5;            // 0..7
    const int bCol = (tid & 31) * 4;      // 0..124

    float acc[8][8];
    #pragma unroll
    for (int i = 0; i < 8; i++)
        #pragma unroll
        for (int j = 0; j < 8; j++) acc[i][j] = 0.f;

    for (int k0 = 0; k0 < K; k0 += 8) {
        float4 a = *(const float4*)(A + (size_t)(rowBase + aRow) * K + k0 + aCol);
        As[aCol + 0][aRow] = a.x;
        As[aCol + 1][aRow] = a.y;
        As[aCol + 2][aRow] = a.z;
        As[aCol + 3][aRow] = a.w;
        float4 b = *(const float4*)(B + (size_t)(k0 + bRow) * N + colBase + bCol);
        *(float4*)&Bs[bRow][bCol] = b;
        __syncthreads();

        #pragma unroll
        for (int k = 0; k < 8; k++) {
            float ra[8], rb[8];
            #pragma unroll
            for (int i = 0; i < 8; i++) ra[i] = As[k][ty * 8 + i];
            #pragma unroll
            for (int j = 0; j < 8; j++) rb[j] = Bs[k][tx * 8 + j];
            #pragma unroll
            for (int i = 0; i < 8; i++)
                #pragma unroll
                for (int j = 0; j < 8; j++) acc[i][j] += ra[i] * rb[j];
        }
        __syncthreads();
    }

    #pragma unroll
    for (int i = 0; i < 8; i++) {
        const size_t row = rowBase + ty * 8 + i;
        #pragma unroll
        for (int j = 0; j < 8; j += 4) {
            const int col = colBase + tx * 8 + j;
            float4 o;
            o.x = acc[i][j + 0] + bias[col + 0];
            o.y = acc[i][j + 1] + bias[col + 1];
            o.z = acc[i][j + 2] + bias[col + 2];
            o.w = acc[i][j + 3] + bias[col + 3];
            *(float4*)(C + row * N + col) = o;
        }
    }
}

// ---------------- kernel 3: per-head LN (q,k) + RoPE + transpose ----------
// one warp per (b,s,h); lane handles elements d and d+32
__global__ __launch_bounds__(128) void qk_rope_kernel(
    const float* __restrict__ qkv,
    const float* __restrict__ q_scale, const float* __restrict__ k_scale,
    float* __restrict__ Q, float* __restrict__ K, float* __restrict__ V)
{
    const int w = blockIdx.x * 4 + (threadIdx.x >> 5);
    const int lane = threadIdx.x & 31;
    const int h = w % HH;
    const int s = (w / HH) % SS;
    const int b = w / (HH * SS);

    const float* row = qkv + (size_t)(b * SS + s) * (3 * DD) + h * HD;
    float q0 = row[lane],        q1 = row[lane + 32];
    float k0 = row[DD + lane],   k1 = row[DD + lane + 32];
    float v0 = row[2*DD + lane], v1 = row[2*DD + lane + 32];

    // ---- q LN ----
    float mu = q0 + q1;
    #pragma unroll
    for (int o = 16; o; o >>= 1) mu += __shfl_xor_sync(0xffffffffu, mu, o);
    mu *= (1.f / 64.f);
    float a0 = q0 - mu, a1 = q1 - mu;
    float var = a0 * a0 + a1 * a1;
    #pragma unroll
    for (int o = 16; o; o >>= 1) var += __shfl_xor_sync(0xffffffffu, var, o);
    float r = rsqrtf(var * (1.f / 64.f) + EPS);
    float yq0 = a0 * r * q_scale[lane], yq1 = a1 * r * q_scale[lane + 32];

    // ---- k LN ----
    mu = k0 + k1;
    #pragma unroll
    for (int o = 16; o; o >>= 1) mu += __shfl_xor_sync(0xffffffffu, mu, o);
    mu *= (1.f / 64.f);
    a0 = k0 - mu; a1 = k1 - mu;
    var = a0 * a0 + a1 * a1;
    #pragma unroll
    for (int o = 16; o; o >>= 1) var += __shfl_xor_sync(0xffffffffu, var, o);
    r = rsqrtf(var * (1.f / 64.f) + EPS);
    float yk0 = a0 * r * k_scale[lane], yk1 = a1 * r * k_scale[lane + 32];

    // ---- RoPE ----
    const float invf = (float)exp(-(double)(2 * lane) / 64.0 * log(10000.0));
    const float ang = (float)s * invf;
    const float c = cosf(ang), sn = sinf(ang);

    float oq0 = yq0 * c - yq1 * sn;
    float oq1 = yq1 * c + yq0 * sn;
    float ok0 = yk0 * c - yk1 * sn;
    float ok1 = yk1 * c + yk0 * sn;

    const size_t base = ((size_t)(b * HH + h) * SS + s) * HD;
    Q[base + lane] = oq0; Q[base + lane + 32] = oq1;
    K[base + lane] = ok0; K[base + lane + 32] = ok1;
    V[base + lane] = v0;  V[base + lane + 32] = v1;
}

// ---------------- kernel 4: flash attention, 64-query tiles ---------------
// block = 64 threads; thread i owns query row i. Query row lives in REGISTERS
// (q[64]); key/value smem reads are warp-broadcast LDS.128 (0.25 LDS/FFMA).
// Online softmax is chunked over 16 keys so live state is q[64]+acc[64]+s[16].
__global__ __launch_bounds__(64) void flash_kernel(
    const float* __restrict__ Q, const float* __restrict__ K,
    const float* __restrict__ V, float* __restrict__ O)
{
    __shared__ float Qs[64 * 64];   // staging, transposed: Qs[k*64 + i]
    __shared__ float Ks[64 * 64];   // Ks[j*64 + k]
    __shared__ float Vs[64 * 64];   // Vs[j*64 + d]

    const int i = threadIdx.x;
    const int bh = blockIdx.y;                 // 0..31
    const int q0 = blockIdx.x * 64;
    const float* Qb = Q + ((size_t)bh * SS + q0) * HD;

    for (int e = i; e < 4096; e += 64)
        Qs[(e & 63) * 64 + (e >> 6)] = Qb[e];
    __syncthreads();

    float q[64];
    #pragma unroll
    for (int kk = 0; kk < 64; kk++) q[kk] = Qs[kk * 64 + i];

    float acc[64];
    #pragma unroll
    for (int d = 0; d < 64; d++) acc[d] = 0.f;
    float m = -1e30f, l = 0.f;

    const float4* Ks4 = (const float4*)Ks;
    const float4* Vs4 = (const float4*)Vs;

    for (int kt = 0; kt < SS / 64; kt++) {
        const float4* Kb4 = (const float4*)(K + ((size_t)bh * SS + kt * 64) * HD);
        const float4* Vb4 = (const float4*)(V + ((size_t)bh * SS + kt * 64) * HD);
        __syncthreads();
        for (int e = i; e < 1024; e += 64) {
            ((float4*)Ks)[e] = Kb4[e];
            ((float4*)Vs)[e] = Vb4[e];
        }
        __syncthreads();

        #pragma unroll 1
        for (int jt = 0; jt < 64; jt += 16) {
            // ---- scores for this 16-key chunk ----
            float s[16];
            float mn = m;
            #pragma unroll
            for (int j = 0; j < 16; j++) {
                float a = 0.f;
                #pragma unroll
                for (int k4 = 0; k4 < 16; k4++) {
                    const float4 kv = Ks4[(jt + j) * 16 + k4];   // broadcast
                    a += q[k4 * 4 + 0] * kv.x;
                    a += q[k4 * 4 + 1] * kv.y;
                    a += q[k4 * 4 + 2] * kv.z;
                    a += q[k4 * 4 + 3] * kv.w;
                }
                a *= 0.125f;                   // 1/sqrt(64)
                s[j] = a;
                mn = fmaxf(mn, a);
            }

            // ---- rescale running state ----
            const float corr = __expf(m - mn);
            l *= corr;
            #pragma unroll
            for (int d = 0; d < 64; d++) acc[d] *= corr;
            m = mn;

            // ---- accumulate P @ V for the chunk ----
            #pragma unroll
            for (int j = 0; j < 16; j++) {
                const float p = __expf(s[j] - mn);
                l += p;
                #pragma unroll
                for (int d4 = 0; d4 < 16; d4++) {
                    const float4 vv = Vs4[(jt + j) * 16 + d4];   // broadcast
                    acc[d4 * 4 + 0] += p * vv.x;
                    acc[d4 * 4 + 1] += p * vv.y;
                    acc[d4 * 4 + 2] += p * vv.z;
                    acc[d4 * 4 + 3] += p * vv.w;
                }
            }
        }
    }

    const int b = bh >> 4, h = bh & 15;
    const float inv = 1.f / l;
    float* Ob = O + ((size_t)(b * SS + q0 + i)) * DD + h * HD;
    #pragma unroll
    for (int d4 = 0; d4 < 16; d4++) {
        float4 o;
        o.x = acc[d4 * 4 + 0] * inv;
        o.y = acc[d4 * 4 + 1] * inv;
        o.z = acc[d4 * 4 + 2] * inv;
        o.w = acc[d4 * 4 + 3] * inv;
        *(float4*)(Ob + d4 * 4) = o;
    }
}

// ---------------- launcher -------------------------------------------------
extern "C" void kernel_launch(void* const* d_in, const int* in_sizes, int n_in,
                              void* d_out, int out_size)
{
    const float* x        = (const float*)d_in[0];
    const float* w_qkv    = (const float*)d_in[1];
    const float* b_qkv    = (const float*)d_in[2];
    const float* w_out    = (const float*)d_in[3];
    const float* b_out    = (const float*)d_in[4];
    const float* ln_scale = (const float*)d_in[5];
    const float* ln_bias  = (const float*)d_in[6];
    const float* q_scale  = (const float*)d_in[7];
    const float* k_scale  = (const float*)d_in[8];
    float* out = (float*)d_out;

    float *xn, *qkv, *q, *k, *v, *attn;
    cudaGetSymbolAddress((void**)&xn,   g_xn);
    cudaGetSymbolAddress((void**)&qkv,  g_qkv);
    cudaGetSymbolAddress((void**)&q,    g_q);
    cudaGetSymbolAddress((void**)&k,    g_k);
    cudaGetSymbolAddress((void**)&v,    g_v);
    cudaGetSymbolAddress((void**)&attn, g_attn);

    // 1) input layernorm
    ln_kernel<<<ROWS, 256>>>(x, ln_scale, ln_bias, xn);

    // 2) QKV projection: [4096,1024] @ [1024,3072]
    sgemm_bias<<<dim3(3 * DD / 128, ROWS / 128), 256>>>(xn, w_qkv, b_qkv, qkv,
                                                        ROWS, 3 * DD, DD);

    // 3) head LN + RoPE + layout change
    qk_rope_kernel<<<(BB * SS * HH) / 4, 128>>>(qkv, q_scale, k_scale, q, k, v);

    // 4) attention
    flash_kernel<<<dim3(SS / 64, BB * HH), 64>>>(q, k, v, attn);

    // 5) output projection: [4096,1024] @ [1024,1024]
    sgemm_bias<<<dim3(DD / 128, ROWS / 128), 256>>>(attn, w_out, b_out, out,
                                                    ROWS, DD, DD);
}